// round 8
// baseline (speedup 1.0000x reference)
#include <cuda_runtime.h>
#include <cuda_bf16.h>
#include <cstdint>

// Problem constants
#define NN   32
#define CC   512
#define HWL  3136        // 56*56
#define GG   8
#define LL   64
#define MTOT 100352      // NN*HWL
#define EPSV 1e-4f
#define NPART 128        // 32 n-chunks * 4 k-chunks
#define RL   68          // smem row length in floats
#define SDW  66          // Sdup row stride in ulls
#define OPOS(o) (8*(o) + 4*((o)>>2))   // word offset of octet o (distinct bank-quads)

typedef unsigned long long ull;

// ---------------- scratch (device globals; no allocation allowed) -------------
__device__ float g_pcov[GG][NPART][LL * LL];  // partial Grams
__device__ float g_psum[GG][NPART][LL];       // partial channel sums
__device__ float g_mu[CC];
__device__ float g_cov[GG * LL * LL];
__device__ float g_subT[GG * LL * LL];        // whitening subspace, TRANSPOSED [g][k][i] = S[i][k]
__device__ float g_t[CC];                     // t[c] = sum_j S[c][j] * mu[g*64+j]

// ---------------- helpers ------------------------------------------------------
__device__ __forceinline__ uint32_t smem_u32(const void* p) {
    uint32_t a;
    asm("{ .reg .u64 t; cvta.to.shared.u64 t, %1; cvt.u32.u64 %0, t; }" : "=r"(a) : "l"(p));
    return a;
}
__device__ __forceinline__ void cpasync16(uint32_t dst, const void* src) {
    asm volatile("cp.async.ca.shared.global [%0], [%1], 16;" :: "r"(dst), "l"(src) : "memory");
}
#define CP_COMMIT() asm volatile("cp.async.commit_group;" ::: "memory")
#define CP_WAIT0()  asm volatile("cp.async.wait_group 0;" ::: "memory")

__device__ __forceinline__ ull ffma2(ull a, ull b, ull c) {
    ull d;
    asm("fma.rn.f32x2 %0, %1, %2, %3;" : "=l"(d) : "l"(a), "l"(b), "l"(c));
    return d;
}
__device__ __forceinline__ ull dup2(float v) {
    ull d;
    asm("mov.b64 %0, {%1, %1};" : "=l"(d) : "f"(v));
    return d;
}
__device__ __forceinline__ float2 unpack2(ull v) {
    float lo, hi;
    asm("mov.b64 {%0, %1}, %2;" : "=f"(lo), "=f"(hi) : "l"(v));
    return make_float2(lo, hi);
}

// =============================================================================
// Kernel 1: partial Gram + partial channel sums.
// grid (4 k-chunks, 32 n, 8 g), 32 threads. Thread tile: 16 a-ch (8 f32x2
// pairs, direct ulonglong2 LDS) x 8 b-ch (dup'd). Smem: [hw][ch] transposed,
// rotated-octet layout (R6-proven, conflict-free). Per k: 64 FFMA2 vs 128
// fma-pipe cycles -> pipe-bound with slack.
// =============================================================================
__global__ __launch_bounds__(32) void k_cov_partial(const float* __restrict__ x) {
    const int q = blockIdx.x;           // k-chunk 0..3
    const int n = blockIdx.y;
    const int g = blockIdx.z;
    __shared__ __align__(16) float Xs[64 * RL];

    const int tid = threadIdx.x;
    const int cg  = tid >> 3;           // a-group: channels 16cg..16cg+15
    const int ob  = tid & 7;            // b-octet: channels 8ob..8ob+7

    const int tiles = (q == 0) ? 13 : 12;
    const int k0    = (q == 0) ? 0 : (832 + (q - 1) * 768);
    const float* base = x + ((size_t)n * CC + (size_t)g * LL) * HWL + k0;

    ull acc[8][8];
    #pragma unroll
    for (int p = 0; p < 8; ++p)
        #pragma unroll
        for (int j = 0; j < 8; ++j) acc[p][j] = 0ull;
    float rs0 = 0.f, rs1 = 0.f;

    for (int tI = 0; tI < tiles; ++tI) {
        __syncthreads();
        // load 64 ch x 64 hw, transpose into Xs[k][*] with octet rotation
        #pragma unroll
        for (int idx = tid; idx < 1024; idx += 32) {
            int r = idx >> 4, c = idx & 15;
            float4 v = *reinterpret_cast<const float4*>(base + (size_t)r * HWL + tI * 64 + c * 4);
            int o = r >> 3, r7 = r & 7;
            float vv[4] = {v.x, v.y, v.z, v.w};
            #pragma unroll
            for (int i = 0; i < 4; ++i) {
                int k = 4 * c + i;
                Xs[k * RL + OPOS((o + k) & 7) + r7] = vv[i];
            }
        }
        __syncthreads();

        #pragma unroll 4
        for (int k = 0; k < 64; ++k) {
            const float* row = Xs + k * RL;
            // rowsums for channels tid and tid+32
            rs0 += row[OPOS((cg + k) & 7) + ob];
            rs1 += row[OPOS((cg + 4 + k) & 7) + ob];

            int oa0 = (2 * cg + k) & 7, oa1 = (2 * cg + 1 + k) & 7;
            ulonglong2 A0 = *reinterpret_cast<const ulonglong2*>(row + OPOS(oa0));
            ulonglong2 A1 = *reinterpret_cast<const ulonglong2*>(row + OPOS(oa0) + 4);
            ulonglong2 A2 = *reinterpret_cast<const ulonglong2*>(row + OPOS(oa1));
            ulonglong2 A3 = *reinterpret_cast<const ulonglong2*>(row + OPOS(oa1) + 4);
            ull A[8] = {A0.x, A0.y, A1.x, A1.y, A2.x, A2.y, A3.x, A3.y};

            int obk = (ob + k) & 7;
            float4 b0 = *reinterpret_cast<const float4*>(row + OPOS(obk));
            float4 b1 = *reinterpret_cast<const float4*>(row + OPOS(obk) + 4);
            ull B[8] = {dup2(b0.x), dup2(b0.y), dup2(b0.z), dup2(b0.w),
                        dup2(b1.x), dup2(b1.y), dup2(b1.z), dup2(b1.w)};

            #pragma unroll
            for (int p = 0; p < 8; ++p)
                #pragma unroll
                for (int j = 0; j < 8; ++j)
                    acc[p][j] = ffma2(A[p], B[j], acc[p][j]);
        }
    }

    const int p = n * 4 + q;
    g_psum[g][p][tid]      = rs0;
    g_psum[g][p][tid + 32] = rs1;
    float* outp = &g_pcov[g][p][0];
    #pragma unroll
    for (int pp = 0; pp < 8; ++pp) {
        float lo[8], hi[8];
        #pragma unroll
        for (int j = 0; j < 8; ++j) {
            float2 f = unpack2(acc[pp][j]);
            lo[j] = f.x; hi[j] = f.y;
        }
        int r0 = 16 * cg + 2 * pp;
        *reinterpret_cast<float4*>(outp + (size_t)r0 * 64 + 8 * ob)           = make_float4(lo[0], lo[1], lo[2], lo[3]);
        *reinterpret_cast<float4*>(outp + (size_t)r0 * 64 + 8 * ob + 4)       = make_float4(lo[4], lo[5], lo[6], lo[7]);
        *reinterpret_cast<float4*>(outp + (size_t)(r0 + 1) * 64 + 8 * ob)     = make_float4(hi[0], hi[1], hi[2], hi[3]);
        *reinterpret_cast<float4*>(outp + (size_t)(r0 + 1) * 64 + 8 * ob + 4) = make_float4(hi[4], hi[5], hi[6], hi[7]);
    }
}

// =============================================================================
// Kernel 2a: reduce channel sums -> mu.  grid 8, 64 threads.
// =============================================================================
__global__ __launch_bounds__(64) void k_mean() {
    const int g = blockIdx.x, i = threadIdx.x;
    float s = 0.f;
    #pragma unroll 4
    for (int p = 0; p < NPART; ++p) s += g_psum[g][p][i];
    g_mu[g * LL + i] = s / (float)MTOT;
}

// =============================================================================
// Kernel 2b: reduce partial Grams -> cov (with -mu mu^T + eps I). grid (16,8).
// =============================================================================
__global__ __launch_bounds__(256) void k_cov_finalize() {
    const int g = blockIdx.y;
    const int e = blockIdx.x * 256 + threadIdx.x;
    const int i = e >> 6, j = e & 63;
    float s0 = 0.f, s1 = 0.f, s2 = 0.f, s3 = 0.f;
    #pragma unroll 4
    for (int p = 0; p < NPART; p += 4) {
        s0 += g_pcov[g][p + 0][e];
        s1 += g_pcov[g][p + 1][e];
        s2 += g_pcov[g][p + 2][e];
        s3 += g_pcov[g][p + 3][e];
    }
    float c = ((s0 + s1) + (s2 + s3)) / (float)MTOT - g_mu[g * LL + i] * g_mu[g * LL + j];
    if (i == j) c += EPSV;
    g_cov[g * LL * LL + e] = c;
}

// =============================================================================
// Kernel 3: power iteration + deflation (unchanged — matched reference in R1).
// =============================================================================
#define MATVEC64(res, Aarr, vptr) {                                        \
    float y0 = 0.f, y1 = 0.f, y2 = 0.f, y3 = 0.f;                          \
    _Pragma("unroll")                                                      \
    for (int j_ = 0; j_ < 64; j_ += 4) {                                   \
        y0 = fmaf(Aarr[j_ + 0], (vptr)[j_ + 0], y0);                       \
        y1 = fmaf(Aarr[j_ + 1], (vptr)[j_ + 1], y1);                       \
        y2 = fmaf(Aarr[j_ + 2], (vptr)[j_ + 2], y2);                       \
        y3 = fmaf(Aarr[j_ + 3], (vptr)[j_ + 3], y3);                       \
    }                                                                      \
    res = (y0 + y1) + (y2 + y3);                                           \
}

__device__ __forceinline__ float sumsq64(const float* v) {
    float y0 = 0.f, y1 = 0.f, y2 = 0.f, y3 = 0.f;
    #pragma unroll
    for (int j = 0; j < 64; j += 4) {
        y0 = fmaf(v[j + 0], v[j + 0], y0);
        y1 = fmaf(v[j + 1], v[j + 1], y1);
        y2 = fmaf(v[j + 2], v[j + 2], y2);
        y3 = fmaf(v[j + 3], v[j + 3], y3);
    }
    return (y0 + y1) + (y2 + y3);
}
__device__ __forceinline__ float dot64(const float* a, const float* b) {
    float y0 = 0.f, y1 = 0.f, y2 = 0.f, y3 = 0.f;
    #pragma unroll
    for (int j = 0; j < 64; j += 4) {
        y0 = fmaf(a[j + 0], b[j + 0], y0);
        y1 = fmaf(a[j + 1], b[j + 1], y1);
        y2 = fmaf(a[j + 2], b[j + 2], y2);
        y3 = fmaf(a[j + 3], b[j + 3], y3);
    }
    return (y0 + y1) + (y2 + y3);
}

__global__ __launch_bounds__(64) void k_pi(const float* __restrict__ vinit) {
    const int g = blockIdx.x, i = threadIdx.x;
    __shared__ float vs[2][64];
    __shared__ float av[64];

    float A[64], S[64];
    #pragma unroll
    for (int j = 0; j < 64; ++j) {
        A[j] = g_cov[g * LL * LL + i * 64 + j];
        S[j] = 0.f;
    }

    float lam_prev = 0.f;

    for (int e = 0; e < 64; ++e) {
        __syncthreads();
        vs[0][i] = vinit[((size_t)g * LL + e) * LL + i];
        __syncthreads();

        float n2  = sumsq64(vs[0]);
        float inv = 1.f / (sqrtf(n2) + 1e-12f);
        int cur = 0;

        #pragma unroll 1
        for (int it = 0; it < 19; ++it) {
            float y;
            MATVEC64(y, A, vs[cur]);
            y *= inv;
            vs[cur ^ 1][i] = y;
            __syncthreads();
            cur ^= 1;
            n2  = sumsq64(vs[cur]);
            inv = 1.f / (sqrtf(n2) + 1e-12f);
        }

        float vi = vs[cur][i] * inv;
        __syncthreads();
        vs[cur ^ 1][i] = vi;
        __syncthreads();
        cur ^= 1;

        float Avi;
        MATVEC64(Avi, A, vs[cur]);
        av[i] = Avi;
        __syncthreads();

        float vAv = dot64(vs[cur], av);
        float vv  = sumsq64(vs[cur]);
        float lam = vAv / vv;

        if (e > 0 && (lam_prev < lam || lam < EPSV)) break;

        float svi = rsqrtf(lam) * vi;
        #pragma unroll
        for (int j = 0; j < 64; ++j) {
            float vj = vs[cur][j];
            S[j] = fmaf(svi, vj, S[j]);
            A[j] = fmaf(-Avi, vj, A[j]);
        }
        lam_prev = lam;
    }

    #pragma unroll
    for (int j = 0; j < 64; ++j) g_subT[g * LL * LL + j * 64 + i] = S[j];

    float t = 0.f;
    #pragma unroll
    for (int j = 0; j < 64; ++j) t = fmaf(S[j], g_mu[g * LL + j], t);
    g_t[g * LL + i] = t;
}

// =============================================================================
// Kernel 4: apply whitening + affine, hw-pairs in lanes (zero MOVs in loop).
// out = (S @ x) * w + (b - t*w).  grid (7 hw-chunks, 32 n, 8 g), 64 threads.
// Thread tile: 8 ch (chg+8u) x 16 hw (octets 2hg, via 2 LDS.128 -> 4 ull).
// Sdup[k][i]=(s,s) ull table (33.8 KB, built once per block); X tiles in
// octet-spread layout, cp.async double-buffered.
// Per k: 32 FFMA2 + 8 LDS.64 + 2 LDS.128 vs 64 fma-pipe cycles.
// =============================================================================
#define AP_SMEM_BYTES (64 * SDW * 8 + 2 * 64 * RL * 4)

__global__ __launch_bounds__(64) void k_apply(const float* __restrict__ x,
                                              const float* __restrict__ wgt,
                                              const float* __restrict__ bia,
                                              float* __restrict__ out) {
    extern __shared__ __align__(16) char smem[];
    ull*   Sd  = reinterpret_cast<ull*>(smem);                 // [64][SDW]
    float* Xb0 = reinterpret_cast<float*>(smem + 64 * SDW * 8);
    float* Xb1 = Xb0 + 64 * RL;

    const int hb = blockIdx.x;            // 0..6 (448 hw each)
    const int n  = blockIdx.y;
    const int g  = blockIdx.z;
    const int tid = threadIdx.x;
    const int chg = tid >> 3;             // ch = chg + 8u, u 0..7
    const int hg  = tid & 7;              // hw octet -> hw 8hg..8hg+7

    const float* xbase = x   + ((size_t)n * CC + (size_t)g * LL) * HWL + hb * 448;
    float*       obase = out + ((size_t)n * CC + (size_t)g * LL) * HWL + hb * 448;

    const uint32_t xs0 = smem_u32(Xb0), xs1 = smem_u32(Xb1);

    // X loader: octet-spread positions (hw-octet c>>1 at OPOS, half c&1)
    #define AP_ISSUE(dst, t) do {                                                   \
        _Pragma("unroll")                                                           \
        for (int idx = tid; idx < 1024; idx += 64) {                                \
            int r = idx >> 4, c = idx & 15;                                         \
            cpasync16((dst) + (uint32_t)(r * RL + OPOS(c >> 1) + 4 * (c & 1)) * 4,  \
                      xbase + (size_t)r * HWL + (t) * 64 + c * 4);                  \
        }                                                                           \
        CP_COMMIT();                                                                \
    } while (0)

    AP_ISSUE(xs0, 0);

    // build Sdup table (overlaps the first cp.async): Sd[k][i] = (S[i][k], S[i][k])
    {
        const float* src = g_subT + g * 4096;
        #pragma unroll
        for (int idx = tid; idx < 4096; idx += 64)
            Sd[(idx >> 6) * SDW + (idx & 63)] = dup2(src[idx]);
    }

    // epilogue constants, duplicated per channel
    ull wd[8], qd[8];
    #pragma unroll
    for (int u = 0; u < 8; ++u) {
        int c = g * LL + chg + 8 * u;
        float w = wgt[c];
        wd[u] = dup2(w);
        qd[u] = dup2(bia[c] - g_t[c] * w);
    }

    for (int t = 0; t < 7; ++t) {
        CP_WAIT0();
        __syncthreads();
        if (t < 6) AP_ISSUE((t & 1) ? xs0 : xs1, t + 1);

        const float* X = (t & 1) ? Xb1 : Xb0;
        ull acc[8][4];
        #pragma unroll
        for (int u = 0; u < 8; ++u)
            #pragma unroll
            for (int e = 0; e < 4; ++e) acc[u][e] = 0ull;

        #pragma unroll 4
        for (int k = 0; k < 64; ++k) {
            const ull* srow = Sd + k * SDW;
            ull a[8];
            #pragma unroll
            for (int u = 0; u < 8; ++u) a[u] = srow[chg + 8 * u];

            const float* xr = X + k * RL;
            ulonglong2 b0 = *reinterpret_cast<const ulonglong2*>(xr + OPOS(hg));
            ulonglong2 b1 = *reinterpret_cast<const ulonglong2*>(xr + OPOS(hg) + 4);

            #pragma unroll
            for (int u = 0; u < 8; ++u) {
                acc[u][0] = ffma2(a[u], b0.x, acc[u][0]);
                acc[u][1] = ffma2(a[u], b0.y, acc[u][1]);
                acc[u][2] = ffma2(a[u], b1.x, acc[u][2]);
                acc[u][3] = ffma2(a[u], b1.y, acc[u][3]);
            }
        }

        // epilogue: out = acc * w + q, 2 STG.128 per channel
        #pragma unroll
        for (int u = 0; u < 8; ++u) {
            float* op = obase + (size_t)(chg + 8 * u) * HWL + t * 64 + 8 * hg;
            ull r0 = ffma2(acc[u][0], wd[u], qd[u]);
            ull r1 = ffma2(acc[u][1], wd[u], qd[u]);
            ull r2 = ffma2(acc[u][2], wd[u], qd[u]);
            ull r3 = ffma2(acc[u][3], wd[u], qd[u]);
            float2 f0 = unpack2(r0), f1 = unpack2(r1), f2 = unpack2(r2), f3 = unpack2(r3);
            *reinterpret_cast<float4*>(op)     = make_float4(f0.x, f0.y, f1.x, f1.y);
            *reinterpret_cast<float4*>(op + 4) = make_float4(f2.x, f2.y, f3.x, f3.y);
        }
        __syncthreads();
    }
    #undef AP_ISSUE
}

// =============================================================================
extern "C" void kernel_launch(void* const* d_in, const int* in_sizes, int n_in,
                              void* d_out, int out_size) {
    const float* x     = (const float*)d_in[0];
    const float* vinit = (const float*)d_in[1];
    const float* wgt   = (const float*)d_in[2];
    const float* bia   = (const float*)d_in[3];
    float* out = (float*)d_out;
    (void)in_sizes; (void)n_in; (void)out_size;

    cudaFuncSetAttribute(k_apply, cudaFuncAttributeMaxDynamicSharedMemorySize, AP_SMEM_BYTES);

    k_cov_partial<<<dim3(4, 32, 8), 32>>>(x);
    k_mean<<<8, 64>>>();
    k_cov_finalize<<<dim3(16, 8), 256>>>();
    k_pi<<<8, 64>>>(vinit);
    k_apply<<<dim3(7, 32, 8), 64, AP_SMEM_BYTES>>>(x, wgt, bia, out);
}